// round 12
// baseline (speedup 1.0000x reference)
#include <cuda_runtime.h>
#include <cstdint>

// HashGridEncoding (16 levels, F=2, T=2^19, base 16, scale 1.5) fused with
// Linear(32 -> 64).  x:[8,131072,3] f32, table:[16,524288,2] f32,
// W:[64,32] f32, b:[64] f32 -> out:[8,131072,64] f32.

#define NLEVELS 16
#define TSIZE   (1u << 19)
#define TMASK   (TSIZE - 1u)
#define HP1     2654435761u
#define HP2     805459861u

// scale_l = f32(16*1.5^l - 1) computed exactly in double.
__constant__ float cScales[NLEVELS] = {
    15.0f, 23.0f, 35.0f, 53.0f, 80.0f, 120.5f, 181.25f, 272.375f,
    409.0625f, 614.09375f, 921.640625f, 1382.9609375f,
    2074.94140625f, 3112.912109375f, 4669.8681640625f, 7005.30224609375f };

__device__ __forceinline__ uint32_t umin32(uint32_t a, uint32_t b) { return a < b ? a : b; }

// packed fp32x2 fma: d = a*b + d (elementwise, exact fp32)
__device__ __forceinline__ void fma2(unsigned long long& d,
                                     unsigned long long a,
                                     unsigned long long b) {
    asm("fma.rn.f32x2 %0, %1, %2, %0;" : "+l"(d) : "l"(a), "l"(b));
}
__device__ __forceinline__ float2 u2f(unsigned long long v) {
    float2 r;
    asm("mov.b64 {%0, %1}, %2;" : "=f"(r.x), "=f"(r.y) : "l"(v));
    return r;
}

// One hashed level gather+interp. __ldcg: cache at L2 with default retention
// (load-bearing; .cs/evict-first demote L2 and regress 2x — R8/R9), bypass
// L1 allocation (no fills, no eviction of L1-resident small dense tables).
__device__ __forceinline__ float2 hashed_level(const float4* __restrict__ tl4,
                                               const float2* __restrict__ tl2,
                                               float xn, float yn, float zn, float s)
{
    const float px = __fadd_rn(__fmul_rn(xn, s), 0.5f);
    const float py = __fadd_rn(__fmul_rn(yn, s), 0.5f);
    const float pz = __fadd_rn(__fmul_rn(zn, s), 0.5f);
    const float fx0 = floorf(px), fy0 = floorf(py), fz0 = floorf(pz);
    const float fx = __fadd_rn(px, -fx0);
    const float fy = __fadd_rn(py, -fy0);
    const float fz = __fadd_rn(pz, -fz0);
    const uint32_t x0 = (uint32_t)fx0;
    const uint32_t y0 = (uint32_t)fy0;
    const uint32_t z0 = (uint32_t)fz0;

    const float wx0 = 1.0f - fx, wx1 = fx;
    const float wy0 = 1.0f - fy, wy1 = fy;
    const float wz0 = 1.0f - fz, wz1 = fz;

    const uint32_t hy0 = y0 * HP1;
    const uint32_t hy1 = hy0 + HP1;
    const uint32_t hz0 = z0 * HP2;
    const uint32_t hz1 = hz0 + HP2;
    const uint32_t x1  = x0 + 1u;
    const bool xodd = (x0 & 1u) != 0u;

    const uint32_t hyz[4] = { hy0 ^ hz0, hy0 ^ hz1, hy1 ^ hz0, hy1 ^ hz1 };
    const float    wyz[4] = { wy0 * wz0, wy0 * wz1, wy1 * wz0, wy1 * wz1 };

    uint32_t i0s[4];
    #pragma unroll
    for (int r = 0; r < 4; ++r) i0s[r] = (x0 ^ hyz[r]) & TMASK;

    float4 v4[4];
    #pragma unroll
    for (int r = 0; r < 4; ++r) v4[r] = __ldcg(tl4 + (i0s[r] >> 1));

    float2 vb[4];
    if (xodd) {
        #pragma unroll
        for (int r = 0; r < 4; ++r)
            vb[r] = __ldcg(tl2 + ((x1 ^ hyz[r]) & TMASK));
    }

    float a0 = 0.0f, a1 = 0.0f;
    #pragma unroll
    for (int r = 0; r < 4; ++r) {
        const bool hi = (i0s[r] & 1u) != 0u;
        const float c0x = hi ? v4[r].z : v4[r].x;
        const float c0y = hi ? v4[r].w : v4[r].y;
        const float ox  = hi ? v4[r].x : v4[r].z;
        const float oy  = hi ? v4[r].y : v4[r].w;
        const float c1x = xodd ? vb[r].x : ox;
        const float c1y = xodd ? vb[r].y : oy;

        const float w0 = wx0 * wyz[r];
        const float w1 = wx1 * wyz[r];
        a0 = fmaf(w0, c0x, a0);
        a1 = fmaf(w0, c0y, a1);
        a0 = fmaf(w1, c1x, a0);
        a1 = fmaf(w1, c1y, a1);
    }
    return make_float2(a0, a1);
}

__global__ __launch_bounds__(128, 6)
void hashgrid_fused_kernel(const float* __restrict__ x,
                           const float* __restrict__ table,
                           const float* __restrict__ W,
                           const float* __restrict__ bias,
                           float* __restrict__ out,
                           int P)
{
    // enc staging: point-major float4 (levels 2k,2k+1), stride 9 float4.
    __shared__ float4 sEnc[128 * 9];
    // W staged once per block: row r at sW4[r*9 + q] (pad 1 float4).
    __shared__ float4 sW4[64 * 9];
    __shared__ float  sB[64];

    const int tid = threadIdx.x;

    // ---- cooperative coalesced W/b load; sync now so warps enter the
    //      matmul phase staggered ----
    {
        const float4* __restrict__ Wg = reinterpret_cast<const float4*>(W);
        #pragma unroll
        for (int i = 0; i < 4; ++i) {
            const int g = tid + 128 * i;
            sW4[(g >> 3) * 9 + (g & 7)] = __ldg(Wg + g);
        }
        if (tid < 64) sB[tid] = __ldg(bias + tid);
    }
    __syncthreads();

    const int p  = blockIdx.x * 128 + tid;
    const int pc = (p < P) ? p : (P - 1);

    const float xn = __fmul_rn(__fadd_rn(x[3 * pc + 0], 1.0f), 0.5f);
    const float yn = __fmul_rn(__fadd_rn(x[3 * pc + 1], 1.0f), 0.5f);
    const float zn = __fmul_rn(__fadd_rn(x[3 * pc + 2], 1.0f), 0.5f);

    const float2* __restrict__ tbl2 = reinterpret_cast<const float2*>(table);
    const float4* __restrict__ tbl4 = reinterpret_cast<const float4*>(table);

    // ---- dense levels 0..3 (fully unrolled, compile-time res).
    //      Levels 0-1 keep default caching (L1-resident); levels 2-3 exceed
    //      the L1D carveout and thrash like hashed levels -> __ldcg. ----
    {
        const uint32_t RES_D[4] = { 16u, 24u, 36u, 54u };
        const float    SC_D[4]  = { 15.0f, 23.0f, 35.0f, 53.0f };
        float keep0 = 0.0f, keep1 = 0.0f;
        #pragma unroll
        for (int l = 0; l < 4; ++l) {
            const float s  = SC_D[l];
            const float px = __fadd_rn(__fmul_rn(xn, s), 0.5f);
            const float py = __fadd_rn(__fmul_rn(yn, s), 0.5f);
            const float pz = __fadd_rn(__fmul_rn(zn, s), 0.5f);
            const float fx0 = floorf(px), fy0 = floorf(py), fz0 = floorf(pz);
            const float fx = __fadd_rn(px, -fx0);
            const float fy = __fadd_rn(py, -fy0);
            const float fz = __fadd_rn(pz, -fz0);
            const uint32_t x0 = (uint32_t)fx0;
            const uint32_t y0 = (uint32_t)fy0;
            const uint32_t z0 = (uint32_t)fz0;

            const float wx0 = 1.0f - fx, wx1 = fx;
            const float wy0 = 1.0f - fy, wy1 = fy;
            const float wz0 = 1.0f - fz, wz1 = fz;

            const uint32_t R   = RES_D[l];
            const uint32_t cx0 = umin32(x0, R - 1u);
            const bool d1      = (x0 < R - 1u);
            const bool xodd    = (x0 & 1u) != 0u;
            const uint32_t iy0 = umin32(y0,      R - 1u) * R;
            const uint32_t iy1 = umin32(y0 + 1u, R - 1u) * R;
            const uint32_t iz0 = umin32(z0,      R - 1u) * (R * R);
            const uint32_t iz1 = umin32(z0 + 1u, R - 1u) * (R * R);

            const uint32_t byz[4] = { iy0 + iz0, iy0 + iz1, iy1 + iz0, iy1 + iz1 };
            const float    wyz[4] = { wy0 * wz0, wy0 * wz1, wy1 * wz0, wy1 * wz1 };

            const float2* tl2 = tbl2 + (size_t)l * TSIZE;
            const float4* tl4 = tbl4 + (size_t)l * (TSIZE / 2);

            uint32_t i0s[4];
            #pragma unroll
            for (int r = 0; r < 4; ++r) i0s[r] = cx0 + byz[r];

            float4 v4[4];
            #pragma unroll
            for (int r = 0; r < 4; ++r)
                v4[r] = (l < 2) ? __ldg(tl4 + (i0s[r] >> 1))
                                : __ldcg(tl4 + (i0s[r] >> 1));

            const bool need2 = d1 && xodd;
            float2 vb[4];
            if (need2) {
                #pragma unroll
                for (int r = 0; r < 4; ++r)
                    vb[r] = (l < 2) ? __ldg(tl2 + (i0s[r] + 1u))
                                    : __ldcg(tl2 + (i0s[r] + 1u));
            }

            float a0 = 0.0f, a1 = 0.0f;
            #pragma unroll
            for (int r = 0; r < 4; ++r) {
                const bool hi = (i0s[r] & 1u) != 0u;
                const float c0x = hi ? v4[r].z : v4[r].x;
                const float c0y = hi ? v4[r].w : v4[r].y;
                const float ox  = hi ? vb[r].x : v4[r].z;
                const float oy  = hi ? vb[r].y : v4[r].w;
                const float c1x = d1 ? ox : c0x;
                const float c1y = d1 ? oy : c0y;

                const float w0 = wx0 * wyz[r];
                const float w1 = wx1 * wyz[r];
                a0 = fmaf(w0, c0x, a0);
                a1 = fmaf(w0, c0y, a1);
                a0 = fmaf(w1, c1x, a0);
                a1 = fmaf(w1, c1y, a1);
            }
            if ((l & 1) == 0) { keep0 = a0; keep1 = a1; }
            else sEnc[tid * 9 + (l >> 1)] = make_float4(keep0, keep1, a0, a1);
        }
    }

    // ---- hashed levels 4..15: rolled loop over 6 level-pairs (unroll 1 to
    //      minimize register pressure for the 6-block occupancy target;
    //      R11 showed unroll 2 is perf-neutral, so its reg cost is waste) ----
    #pragma unroll 1
    for (int lp = 2; lp < 8; ++lp) {
        const int l0 = 2 * lp;
        const float2 rA = hashed_level(tbl4 + (size_t)l0 * (TSIZE / 2),
                                       tbl2 + (size_t)l0 * TSIZE,
                                       xn, yn, zn, cScales[l0]);
        const float2 rB = hashed_level(tbl4 + (size_t)(l0 + 1) * (TSIZE / 2),
                                       tbl2 + (size_t)(l0 + 1) * TSIZE,
                                       xn, yn, zn, cScales[l0 + 1]);
        sEnc[tid * 9 + lp] = make_float4(rA.x, rA.y, rB.x, rB.y);
    }

    __syncwarp();   // sEnc is per-warp

    // ---- Linear(32 -> 64), packed fp32x2 FMA ----
    const int lane  = tid & 31;
    const int wbase = tid & ~31;
    const int gbase = blockIdx.x * 128 + wbase;

    const ulonglong2* __restrict__ sWp = reinterpret_cast<const ulonglong2*>(sW4);
    ulonglong2 wa[8], wb[8];
    #pragma unroll
    for (int q = 0; q < 8; ++q) {
        wa[q] = sWp[lane * 9 + q];
        wb[q] = sWp[(lane + 32) * 9 + q];
    }
    const float bA = sB[lane];
    const float bB = sB[lane + 32];

    #pragma unroll 1
    for (int q = 0; q < 32; ++q) {
        const ulonglong2* e =
            reinterpret_cast<const ulonglong2*>(&sEnc[(wbase + q) * 9]);
        unsigned long long A0 = 0ull, A1 = 0ull, B0 = 0ull, B1 = 0ull;
        #pragma unroll
        for (int k = 0; k < 8; ++k) {
            const ulonglong2 ev = e[k];        // uniform LDS.128 broadcast
            fma2(A0, ev.x, wa[k].x);
            fma2(A1, ev.y, wa[k].y);
            fma2(B0, ev.x, wb[k].x);
            fma2(B1, ev.y, wb[k].y);
        }
        const float2 fa0 = u2f(A0), fa1 = u2f(A1);
        const float2 fb0 = u2f(B0), fb1 = u2f(B1);
        const float aA = bA + fa0.x + fa0.y + fa1.x + fa1.y;
        const float aB = bB + fb0.x + fb0.y + fb1.x + fb1.y;

        const int gp = gbase + q;
        if (gp < P) {
            out[(size_t)gp * 64 + lane]      = aA;     // 128B coalesced
            out[(size_t)gp * 64 + 32 + lane] = aB;     // 128B coalesced
        }
    }
}

extern "C" void kernel_launch(void* const* d_in, const int* in_sizes, int n_in,
                              void* d_out, int out_size)
{
    const float* x     = (const float*)d_in[0];
    const float* table = (const float*)d_in[1];
    const float* W     = (const float*)d_in[2];
    const float* b     = (const float*)d_in[3];
    float* out = (float*)d_out;

    const int P    = in_sizes[0] / 3;          // 1,048,576 points
    const int grid = (P + 127) / 128;
    hashgrid_fused_kernel<<<grid, 128>>>(x, table, W, b, out, P);
}

// round 13
// speedup vs baseline: 1.2200x; 1.2200x over previous
#include <cuda_runtime.h>
#include <cstdint>

// HashGridEncoding (16 levels, F=2, T=2^19, base 16, scale 1.5) fused with
// Linear(32 -> 64).  x:[8,131072,3] f32, table:[16,524288,2] f32,
// W:[64,32] f32, b:[64] f32 -> out:[8,131072,64] f32.
//
// Final configuration (empirical optimum over 12 rounds):
//  - 1 thread/point, 128-thread blocks, __launch_bounds__(128,5): 96 regs /
//    20 warps/SM is the measured sweet spot (128reg/16w: L1 82%; 80reg/24w:
//    gather serialization, 69% L1, +28% time).
//  - x-corner pairing: tcnn's x-prime is 1, so the two x-corners of a cell
//    are table entries i and i^1 (hashed) / i and i+1 (dense): one aligned
//    float4 covers both when i is even; odd case adds one predicated float2.
//  - hashed gathers use __ldcg (L2-cached, L1-bypass): preserves load-bearing
//    L2 table residency (evict-first hints demote L2 on sm_103a: 2x slower),
//    while avoiding L1 fills/pollution (-1% vs __ldg).
//  - Linear(32->64): W staged per-block in padded smem, warp-uniform LDS.128
//    enc broadcasts, packed fp32x2 FMA (exact fp32), 128B-coalesced stores.

#define NLEVELS 16
#define TSIZE   (1u << 19)
#define TMASK   (TSIZE - 1u)
#define HP1     2654435761u
#define HP2     805459861u

// scale_l = f32(16*1.5^l - 1) computed exactly in double.
__constant__ float cScales[NLEVELS] = {
    15.0f, 23.0f, 35.0f, 53.0f, 80.0f, 120.5f, 181.25f, 272.375f,
    409.0625f, 614.09375f, 921.640625f, 1382.9609375f,
    2074.94140625f, 3112.912109375f, 4669.8681640625f, 7005.30224609375f };

__device__ __forceinline__ uint32_t umin32(uint32_t a, uint32_t b) { return a < b ? a : b; }

// packed fp32x2 fma: d = a*b + d (elementwise, exact fp32)
__device__ __forceinline__ void fma2(unsigned long long& d,
                                     unsigned long long a,
                                     unsigned long long b) {
    asm("fma.rn.f32x2 %0, %1, %2, %0;" : "+l"(d) : "l"(a), "l"(b));
}
__device__ __forceinline__ float2 u2f(unsigned long long v) {
    float2 r;
    asm("mov.b64 {%0, %1}, %2;" : "=f"(r.x), "=f"(r.y) : "l"(v));
    return r;
}

// One hashed level gather+interp (loads via __ldcg; see header comment).
__device__ __forceinline__ float2 hashed_level(const float4* __restrict__ tl4,
                                               const float2* __restrict__ tl2,
                                               float xn, float yn, float zn, float s)
{
    const float px = __fadd_rn(__fmul_rn(xn, s), 0.5f);
    const float py = __fadd_rn(__fmul_rn(yn, s), 0.5f);
    const float pz = __fadd_rn(__fmul_rn(zn, s), 0.5f);
    const float fx0 = floorf(px), fy0 = floorf(py), fz0 = floorf(pz);
    const float fx = __fadd_rn(px, -fx0);
    const float fy = __fadd_rn(py, -fy0);
    const float fz = __fadd_rn(pz, -fz0);
    const uint32_t x0 = (uint32_t)fx0;
    const uint32_t y0 = (uint32_t)fy0;
    const uint32_t z0 = (uint32_t)fz0;

    const float wx0 = 1.0f - fx, wx1 = fx;
    const float wy0 = 1.0f - fy, wy1 = fy;
    const float wz0 = 1.0f - fz, wz1 = fz;

    const uint32_t hy0 = y0 * HP1;
    const uint32_t hy1 = hy0 + HP1;
    const uint32_t hz0 = z0 * HP2;
    const uint32_t hz1 = hz0 + HP2;
    const uint32_t x1  = x0 + 1u;
    const bool xodd = (x0 & 1u) != 0u;

    const uint32_t hyz[4] = { hy0 ^ hz0, hy0 ^ hz1, hy1 ^ hz0, hy1 ^ hz1 };
    const float    wyz[4] = { wy0 * wz0, wy0 * wz1, wy1 * wz0, wy1 * wz1 };

    uint32_t i0s[4];
    #pragma unroll
    for (int r = 0; r < 4; ++r) i0s[r] = (x0 ^ hyz[r]) & TMASK;

    float4 v4[4];
    #pragma unroll
    for (int r = 0; r < 4; ++r) v4[r] = __ldcg(tl4 + (i0s[r] >> 1));

    float2 vb[4];
    if (xodd) {
        #pragma unroll
        for (int r = 0; r < 4; ++r)
            vb[r] = __ldcg(tl2 + ((x1 ^ hyz[r]) & TMASK));
    }

    float a0 = 0.0f, a1 = 0.0f;
    #pragma unroll
    for (int r = 0; r < 4; ++r) {
        const bool hi = (i0s[r] & 1u) != 0u;
        const float c0x = hi ? v4[r].z : v4[r].x;
        const float c0y = hi ? v4[r].w : v4[r].y;
        const float ox  = hi ? v4[r].x : v4[r].z;
        const float oy  = hi ? v4[r].y : v4[r].w;
        const float c1x = xodd ? vb[r].x : ox;
        const float c1y = xodd ? vb[r].y : oy;

        const float w0 = wx0 * wyz[r];
        const float w1 = wx1 * wyz[r];
        a0 = fmaf(w0, c0x, a0);
        a1 = fmaf(w0, c0y, a1);
        a0 = fmaf(w1, c1x, a0);
        a1 = fmaf(w1, c1y, a1);
    }
    return make_float2(a0, a1);
}

__global__ __launch_bounds__(128, 5)
void hashgrid_fused_kernel(const float* __restrict__ x,
                           const float* __restrict__ table,
                           const float* __restrict__ W,
                           const float* __restrict__ bias,
                           float* __restrict__ out,
                           int P)
{
    // enc staging: point-major float4 (levels 2k,2k+1), stride 9 float4.
    __shared__ float4 sEnc[128 * 9];
    // W staged once per block: row r at sW4[r*9 + q] (pad 1 float4).
    __shared__ float4 sW4[64 * 9];
    __shared__ float  sB[64];

    const int tid = threadIdx.x;

    // ---- cooperative coalesced W/b load; sync now so warps enter the
    //      matmul phase staggered ----
    {
        const float4* __restrict__ Wg = reinterpret_cast<const float4*>(W);
        #pragma unroll
        for (int i = 0; i < 4; ++i) {
            const int g = tid + 128 * i;            // 512 float4 total
            sW4[(g >> 3) * 9 + (g & 7)] = __ldg(Wg + g);
        }
        if (tid < 64) sB[tid] = __ldg(bias + tid);
    }
    __syncthreads();

    const int p  = blockIdx.x * 128 + tid;
    const int pc = (p < P) ? p : (P - 1);

    const float xn = __fmul_rn(__fadd_rn(x[3 * pc + 0], 1.0f), 0.5f);
    const float yn = __fmul_rn(__fadd_rn(x[3 * pc + 1], 1.0f), 0.5f);
    const float zn = __fmul_rn(__fadd_rn(x[3 * pc + 2], 1.0f), 0.5f);

    const float2* __restrict__ tbl2 = reinterpret_cast<const float2*>(table);
    const float4* __restrict__ tbl4 = reinterpret_cast<const float4*>(table);

    // ---- dense levels 0..3 (fully unrolled, compile-time res); default
    //      caching (__ldg) ----
    {
        const uint32_t RES_D[4] = { 16u, 24u, 36u, 54u };
        const float    SC_D[4]  = { 15.0f, 23.0f, 35.0f, 53.0f };
        float keep0 = 0.0f, keep1 = 0.0f;
        #pragma unroll
        for (int l = 0; l < 4; ++l) {
            const float s  = SC_D[l];
            const float px = __fadd_rn(__fmul_rn(xn, s), 0.5f);
            const float py = __fadd_rn(__fmul_rn(yn, s), 0.5f);
            const float pz = __fadd_rn(__fmul_rn(zn, s), 0.5f);
            const float fx0 = floorf(px), fy0 = floorf(py), fz0 = floorf(pz);
            const float fx = __fadd_rn(px, -fx0);
            const float fy = __fadd_rn(py, -fy0);
            const float fz = __fadd_rn(pz, -fz0);
            const uint32_t x0 = (uint32_t)fx0;
            const uint32_t y0 = (uint32_t)fy0;
            const uint32_t z0 = (uint32_t)fz0;

            const float wx0 = 1.0f - fx, wx1 = fx;
            const float wy0 = 1.0f - fy, wy1 = fy;
            const float wz0 = 1.0f - fz, wz1 = fz;

            const uint32_t R   = RES_D[l];
            const uint32_t cx0 = umin32(x0, R - 1u);
            const bool d1      = (x0 < R - 1u);
            const bool xodd    = (x0 & 1u) != 0u;
            const uint32_t iy0 = umin32(y0,      R - 1u) * R;
            const uint32_t iy1 = umin32(y0 + 1u, R - 1u) * R;
            const uint32_t iz0 = umin32(z0,      R - 1u) * (R * R);
            const uint32_t iz1 = umin32(z0 + 1u, R - 1u) * (R * R);

            const uint32_t byz[4] = { iy0 + iz0, iy0 + iz1, iy1 + iz0, iy1 + iz1 };
            const float    wyz[4] = { wy0 * wz0, wy0 * wz1, wy1 * wz0, wy1 * wz1 };

            const float2* tl2 = tbl2 + (size_t)l * TSIZE;
            const float4* tl4 = tbl4 + (size_t)l * (TSIZE / 2);

            uint32_t i0s[4];
            #pragma unroll
            for (int r = 0; r < 4; ++r) i0s[r] = cx0 + byz[r];

            float4 v4[4];
            #pragma unroll
            for (int r = 0; r < 4; ++r) v4[r] = __ldg(tl4 + (i0s[r] >> 1));

            const bool need2 = d1 && xodd;
            float2 vb[4];
            if (need2) {
                #pragma unroll
                for (int r = 0; r < 4; ++r) vb[r] = __ldg(tl2 + (i0s[r] + 1u));
            }

            float a0 = 0.0f, a1 = 0.0f;
            #pragma unroll
            for (int r = 0; r < 4; ++r) {
                const bool hi = (i0s[r] & 1u) != 0u;
                const float c0x = hi ? v4[r].z : v4[r].x;
                const float c0y = hi ? v4[r].w : v4[r].y;
                const float ox  = hi ? vb[r].x : v4[r].z;
                const float oy  = hi ? vb[r].y : v4[r].w;
                const float c1x = d1 ? ox : c0x;
                const float c1y = d1 ? oy : c0y;

                const float w0 = wx0 * wyz[r];
                const float w1 = wx1 * wyz[r];
                a0 = fmaf(w0, c0x, a0);
                a1 = fmaf(w0, c0y, a1);
                a0 = fmaf(w1, c1x, a0);
                a1 = fmaf(w1, c1y, a1);
            }
            if ((l & 1) == 0) { keep0 = a0; keep1 = a1; }
            else sEnc[tid * 9 + (l >> 1)] = make_float4(keep0, keep1, a0, a1);
        }
    }

    // ---- hashed levels 4..15: rolled loop over 6 level-pairs ----
    #pragma unroll 1
    for (int lp = 2; lp < 8; ++lp) {
        const int l0 = 2 * lp;
        const float2 rA = hashed_level(tbl4 + (size_t)l0 * (TSIZE / 2),
                                       tbl2 + (size_t)l0 * TSIZE,
                                       xn, yn, zn, cScales[l0]);
        const float2 rB = hashed_level(tbl4 + (size_t)(l0 + 1) * (TSIZE / 2),
                                       tbl2 + (size_t)(l0 + 1) * TSIZE,
                                       xn, yn, zn, cScales[l0 + 1]);
        sEnc[tid * 9 + lp] = make_float4(rA.x, rA.y, rB.x, rB.y);
    }

    __syncwarp();   // sEnc is per-warp

    // ---- Linear(32 -> 64), packed fp32x2 FMA ----
    const int lane  = tid & 31;
    const int wbase = tid & ~31;
    const int gbase = blockIdx.x * 128 + wbase;

    const ulonglong2* __restrict__ sWp = reinterpret_cast<const ulonglong2*>(sW4);
    ulonglong2 wa[8], wb[8];
    #pragma unroll
    for (int q = 0; q < 8; ++q) {
        wa[q] = sWp[lane * 9 + q];
        wb[q] = sWp[(lane + 32) * 9 + q];
    }
    const float bA = sB[lane];
    const float bB = sB[lane + 32];

    #pragma unroll 1
    for (int q = 0; q < 32; ++q) {
        const ulonglong2* e =
            reinterpret_cast<const ulonglong2*>(&sEnc[(wbase + q) * 9]);
        unsigned long long A0 = 0ull, A1 = 0ull, B0 = 0ull, B1 = 0ull;
        #pragma unroll
        for (int k = 0; k < 8; ++k) {
            const ulonglong2 ev = e[k];        // uniform LDS.128 broadcast
            fma2(A0, ev.x, wa[k].x);
            fma2(A1, ev.y, wa[k].y);
            fma2(B0, ev.x, wb[k].x);
            fma2(B1, ev.y, wb[k].y);
        }
        const float2 fa0 = u2f(A0), fa1 = u2f(A1);
        const float2 fb0 = u2f(B0), fb1 = u2f(B1);
        const float aA = bA + fa0.x + fa0.y + fa1.x + fa1.y;
        const float aB = bB + fb0.x + fb0.y + fb1.x + fb1.y;

        const int gp = gbase + q;
        if (gp < P) {
            out[(size_t)gp * 64 + lane]      = aA;     // 128B coalesced
            out[(size_t)gp * 64 + 32 + lane] = aB;     // 128B coalesced
        }
    }
}

extern "C" void kernel_launch(void* const* d_in, const int* in_sizes, int n_in,
                              void* d_out, int out_size)
{
    const float* x     = (const float*)d_in[0];
    const float* table = (const float*)d_in[1];
    const float* W     = (const float*)d_in[2];
    const float* b     = (const float*)d_in[3];
    float* out = (float*)d_out;

    const int P    = in_sizes[0] / 3;          // 1,048,576 points
    const int grid = (P + 127) / 128;
    hashgrid_fused_kernel<<<grid, 128>>>(x, table, W, b, out, P);
}

// round 14
// speedup vs baseline: 1.2810x; 1.0500x over previous
#include <cuda_runtime.h>
#include <cstdint>

// HashGridEncoding (16 levels, F=2, T=2^19, base 16, scale 1.5) fused with
// Linear(32 -> 64).  x:[8,131072,3] f32, table:[16,524288,2] f32,
// W:[64,32] f32, b:[64] f32 -> out:[8,131072,64] f32.
//
// FINAL configuration (empirical optimum over 13 rounds; bench noise ~±5%):
//  - 1 thread/point, 128-thread blocks, __launch_bounds__(128,5): 96 regs /
//    20 warps/SM is the measured sweet spot (128reg/16w: L1 82%; 80reg/24w:
//    gather load serialization under register pressure, 69% L1, +28% time).
//  - x-corner pairing: tcnn's x-prime is 1, so the two x-corners of a cell
//    are table entries i and i^1 (hashed) / i and i+1 (dense): one aligned
//    float4 covers both when i is even; odd case adds one predicated float2.
//  - streaming gathers (hashed levels + dense 2-3, whose tables exceed the
//    L1D carveout) use __ldcg: L2-cached with DEFAULT retention (evict-first
//    hints demote L2 residency on sm_103a -> 2x slower, measured), L1-bypass
//    (no fills, no eviction of the L1-resident dense 0-1 tables).
//  - Linear(32->64): W staged per-block in padded smem, warp-uniform LDS.128
//    enc broadcasts, packed fp32x2 FMA (exact fp32), 128B-coalesced stores.

#define NLEVELS 16
#define TSIZE   (1u << 19)
#define TMASK   (TSIZE - 1u)
#define HP1     2654435761u
#define HP2     805459861u

// scale_l = f32(16*1.5^l - 1) computed exactly in double.
__constant__ float cScales[NLEVELS] = {
    15.0f, 23.0f, 35.0f, 53.0f, 80.0f, 120.5f, 181.25f, 272.375f,
    409.0625f, 614.09375f, 921.640625f, 1382.9609375f,
    2074.94140625f, 3112.912109375f, 4669.8681640625f, 7005.30224609375f };

__device__ __forceinline__ uint32_t umin32(uint32_t a, uint32_t b) { return a < b ? a : b; }

// packed fp32x2 fma: d = a*b + d (elementwise, exact fp32)
__device__ __forceinline__ void fma2(unsigned long long& d,
                                     unsigned long long a,
                                     unsigned long long b) {
    asm("fma.rn.f32x2 %0, %1, %2, %0;" : "+l"(d) : "l"(a), "l"(b));
}
__device__ __forceinline__ float2 u2f(unsigned long long v) {
    float2 r;
    asm("mov.b64 {%0, %1}, %2;" : "=f"(r.x), "=f"(r.y) : "l"(v));
    return r;
}

// One hashed level gather+interp (loads via __ldcg; see header comment).
__device__ __forceinline__ float2 hashed_level(const float4* __restrict__ tl4,
                                               const float2* __restrict__ tl2,
                                               float xn, float yn, float zn, float s)
{
    const float px = __fadd_rn(__fmul_rn(xn, s), 0.5f);
    const float py = __fadd_rn(__fmul_rn(yn, s), 0.5f);
    const float pz = __fadd_rn(__fmul_rn(zn, s), 0.5f);
    const float fx0 = floorf(px), fy0 = floorf(py), fz0 = floorf(pz);
    const float fx = __fadd_rn(px, -fx0);
    const float fy = __fadd_rn(py, -fy0);
    const float fz = __fadd_rn(pz, -fz0);
    const uint32_t x0 = (uint32_t)fx0;
    const uint32_t y0 = (uint32_t)fy0;
    const uint32_t z0 = (uint32_t)fz0;

    const float wx0 = 1.0f - fx, wx1 = fx;
    const float wy0 = 1.0f - fy, wy1 = fy;
    const float wz0 = 1.0f - fz, wz1 = fz;

    const uint32_t hy0 = y0 * HP1;
    const uint32_t hy1 = hy0 + HP1;
    const uint32_t hz0 = z0 * HP2;
    const uint32_t hz1 = hz0 + HP2;
    const uint32_t x1  = x0 + 1u;
    const bool xodd = (x0 & 1u) != 0u;

    const uint32_t hyz[4] = { hy0 ^ hz0, hy0 ^ hz1, hy1 ^ hz0, hy1 ^ hz1 };
    const float    wyz[4] = { wy0 * wz0, wy0 * wz1, wy1 * wz0, wy1 * wz1 };

    uint32_t i0s[4];
    #pragma unroll
    for (int r = 0; r < 4; ++r) i0s[r] = (x0 ^ hyz[r]) & TMASK;

    float4 v4[4];
    #pragma unroll
    for (int r = 0; r < 4; ++r) v4[r] = __ldcg(tl4 + (i0s[r] >> 1));

    float2 vb[4];
    if (xodd) {
        #pragma unroll
        for (int r = 0; r < 4; ++r)
            vb[r] = __ldcg(tl2 + ((x1 ^ hyz[r]) & TMASK));
    }

    float a0 = 0.0f, a1 = 0.0f;
    #pragma unroll
    for (int r = 0; r < 4; ++r) {
        const bool hi = (i0s[r] & 1u) != 0u;
        const float c0x = hi ? v4[r].z : v4[r].x;
        const float c0y = hi ? v4[r].w : v4[r].y;
        const float ox  = hi ? v4[r].x : v4[r].z;
        const float oy  = hi ? v4[r].y : v4[r].w;
        const float c1x = xodd ? vb[r].x : ox;
        const float c1y = xodd ? vb[r].y : oy;

        const float w0 = wx0 * wyz[r];
        const float w1 = wx1 * wyz[r];
        a0 = fmaf(w0, c0x, a0);
        a1 = fmaf(w0, c0y, a1);
        a0 = fmaf(w1, c1x, a0);
        a1 = fmaf(w1, c1y, a1);
    }
    return make_float2(a0, a1);
}

__global__ __launch_bounds__(128, 5)
void hashgrid_fused_kernel(const float* __restrict__ x,
                           const float* __restrict__ table,
                           const float* __restrict__ W,
                           const float* __restrict__ bias,
                           float* __restrict__ out,
                           int P)
{
    // enc staging: point-major float4 (levels 2k,2k+1), stride 9 float4.
    __shared__ float4 sEnc[128 * 9];
    // W staged once per block: row r at sW4[r*9 + q] (pad 1 float4).
    __shared__ float4 sW4[64 * 9];
    __shared__ float  sB[64];

    const int tid = threadIdx.x;

    // ---- cooperative coalesced W/b load; sync now so warps enter the
    //      matmul phase staggered ----
    {
        const float4* __restrict__ Wg = reinterpret_cast<const float4*>(W);
        #pragma unroll
        for (int i = 0; i < 4; ++i) {
            const int g = tid + 128 * i;            // 512 float4 total
            sW4[(g >> 3) * 9 + (g & 7)] = __ldg(Wg + g);
        }
        if (tid < 64) sB[tid] = __ldg(bias + tid);
    }
    __syncthreads();

    const int p  = blockIdx.x * 128 + tid;
    const int pc = (p < P) ? p : (P - 1);

    const float xn = __fmul_rn(__fadd_rn(x[3 * pc + 0], 1.0f), 0.5f);
    const float yn = __fmul_rn(__fadd_rn(x[3 * pc + 1], 1.0f), 0.5f);
    const float zn = __fmul_rn(__fadd_rn(x[3 * pc + 2], 1.0f), 0.5f);

    const float2* __restrict__ tbl2 = reinterpret_cast<const float2*>(table);
    const float4* __restrict__ tbl4 = reinterpret_cast<const float4*>(table);

    // ---- dense levels 0..3 (fully unrolled, compile-time res).
    //      Levels 0-1 (32KB/110KB, heavy line sharing) keep default caching;
    //      levels 2-3 (373KB/1.26MB) exceed the ~88KB L1D carveout and
    //      thrash like hashed levels -> __ldcg. ----
    {
        const uint32_t RES_D[4] = { 16u, 24u, 36u, 54u };
        const float    SC_D[4]  = { 15.0f, 23.0f, 35.0f, 53.0f };
        float keep0 = 0.0f, keep1 = 0.0f;
        #pragma unroll
        for (int l = 0; l < 4; ++l) {
            const float s  = SC_D[l];
            const float px = __fadd_rn(__fmul_rn(xn, s), 0.5f);
            const float py = __fadd_rn(__fmul_rn(yn, s), 0.5f);
            const float pz = __fadd_rn(__fmul_rn(zn, s), 0.5f);
            const float fx0 = floorf(px), fy0 = floorf(py), fz0 = floorf(pz);
            const float fx = __fadd_rn(px, -fx0);
            const float fy = __fadd_rn(py, -fy0);
            const float fz = __fadd_rn(pz, -fz0);
            const uint32_t x0 = (uint32_t)fx0;
            const uint32_t y0 = (uint32_t)fy0;
            const uint32_t z0 = (uint32_t)fz0;

            const float wx0 = 1.0f - fx, wx1 = fx;
            const float wy0 = 1.0f - fy, wy1 = fy;
            const float wz0 = 1.0f - fz, wz1 = fz;

            const uint32_t R   = RES_D[l];
            const uint32_t cx0 = umin32(x0, R - 1u);
            const bool d1      = (x0 < R - 1u);
            const bool xodd    = (x0 & 1u) != 0u;
            const uint32_t iy0 = umin32(y0,      R - 1u) * R;
            const uint32_t iy1 = umin32(y0 + 1u, R - 1u) * R;
            const uint32_t iz0 = umin32(z0,      R - 1u) * (R * R);
            const uint32_t iz1 = umin32(z0 + 1u, R - 1u) * (R * R);

            const uint32_t byz[4] = { iy0 + iz0, iy0 + iz1, iy1 + iz0, iy1 + iz1 };
            const float    wyz[4] = { wy0 * wz0, wy0 * wz1, wy1 * wz0, wy1 * wz1 };

            const float2* tl2 = tbl2 + (size_t)l * TSIZE;
            const float4* tl4 = tbl4 + (size_t)l * (TSIZE / 2);

            uint32_t i0s[4];
            #pragma unroll
            for (int r = 0; r < 4; ++r) i0s[r] = cx0 + byz[r];

            float4 v4[4];
            #pragma unroll
            for (int r = 0; r < 4; ++r)
                v4[r] = (l < 2) ? __ldg(tl4 + (i0s[r] >> 1))
                                : __ldcg(tl4 + (i0s[r] >> 1));

            const bool need2 = d1 && xodd;
            float2 vb[4];
            if (need2) {
                #pragma unroll
                for (int r = 0; r < 4; ++r)
                    vb[r] = (l < 2) ? __ldg(tl2 + (i0s[r] + 1u))
                                    : __ldcg(tl2 + (i0s[r] + 1u));
            }

            float a0 = 0.0f, a1 = 0.0f;
            #pragma unroll
            for (int r = 0; r < 4; ++r) {
                const bool hi = (i0s[r] & 1u) != 0u;
                const float c0x = hi ? v4[r].z : v4[r].x;
                const float c0y = hi ? v4[r].w : v4[r].y;
                const float ox  = hi ? vb[r].x : v4[r].z;
                const float oy  = hi ? vb[r].y : v4[r].w;
                const float c1x = d1 ? ox : c0x;
                const float c1y = d1 ? oy : c0y;

                const float w0 = wx0 * wyz[r];
                const float w1 = wx1 * wyz[r];
                a0 = fmaf(w0, c0x, a0);
                a1 = fmaf(w0, c0y, a1);
                a0 = fmaf(w1, c1x, a0);
                a1 = fmaf(w1, c1y, a1);
            }
            if ((l & 1) == 0) { keep0 = a0; keep1 = a1; }
            else sEnc[tid * 9 + (l >> 1)] = make_float4(keep0, keep1, a0, a1);
        }
    }

    // ---- hashed levels 4..15: loop over 6 level-pairs, unrolled x2 ----
    #pragma unroll 2
    for (int lp = 2; lp < 8; ++lp) {
        const int l0 = 2 * lp;
        const float2 rA = hashed_level(tbl4 + (size_t)l0 * (TSIZE / 2),
                                       tbl2 + (size_t)l0 * TSIZE,
                                       xn, yn, zn, cScales[l0]);
        const float2 rB = hashed_level(tbl4 + (size_t)(l0 + 1) * (TSIZE / 2),
                                       tbl2 + (size_t)(l0 + 1) * TSIZE,
                                       xn, yn, zn, cScales[l0 + 1]);
        sEnc[tid * 9 + lp] = make_float4(rA.x, rA.y, rB.x, rB.y);
    }

    __syncwarp();   // sEnc is per-warp

    // ---- Linear(32 -> 64), packed fp32x2 FMA ----
    const int lane  = tid & 31;
    const int wbase = tid & ~31;
    const int gbase = blockIdx.x * 128 + wbase;

    const ulonglong2* __restrict__ sWp = reinterpret_cast<const ulonglong2*>(sW4);
    ulonglong2 wa[8], wb[8];
    #pragma unroll
    for (int q = 0; q < 8; ++q) {
        wa[q] = sWp[lane * 9 + q];
        wb[q] = sWp[(lane + 32) * 9 + q];
    }
    const float bA = sB[lane];
    const float bB = sB[lane + 32];

    #pragma unroll 1
    for (int q = 0; q < 32; ++q) {
        const ulonglong2* e =
            reinterpret_cast<const ulonglong2*>(&sEnc[(wbase + q) * 9]);
        unsigned long long A0 = 0ull, A1 = 0ull, B0 = 0ull, B1 = 0ull;
        #pragma unroll
        for (int k = 0; k < 8; ++k) {
            const ulonglong2 ev = e[k];        // uniform LDS.128 broadcast
            fma2(A0, ev.x, wa[k].x);
            fma2(A1, ev.y, wa[k].y);
            fma2(B0, ev.x, wb[k].x);
            fma2(B1, ev.y, wb[k].y);
        }
        const float2 fa0 = u2f(A0), fa1 = u2f(A1);
        const float2 fb0 = u2f(B0), fb1 = u2f(B1);
        const float aA = bA + fa0.x + fa0.y + fa1.x + fa1.y;
        const float aB = bB + fb0.x + fb0.y + fb1.x + fb1.y;

        const int gp = gbase + q;
        if (gp < P) {
            out[(size_t)gp * 64 + lane]      = aA;     // 128B coalesced
            out[(size_t)gp * 64 + 32 + lane] = aB;     // 128B coalesced
        }
    }
}

extern "C" void kernel_launch(void* const* d_in, const int* in_sizes, int n_in,
                              void* d_out, int out_size)
{
    const float* x     = (const float*)d_in[0];
    const float* table = (const float*)d_in[1];
    const float* W     = (const float*)d_in[2];
    const float* b     = (const float*)d_in[3];
    float* out = (float*)d_out;

    const int P    = in_sizes[0] / 3;          // 1,048,576 points
    const int grid = (P + 127) / 128;
    hashgrid_fused_kernel<<<grid, 128>>>(x, table, W, b, out, P);
}